// round 13
// baseline (speedup 1.0000x reference)
#include <cuda_runtime.h>
#include <stdint.h>

#define BB 4
#define CC 256
#define DQK 32
#define NN 4096
#define TQ 128          // queries per CTA
#define KT 32           // keys per tile
#define NKT (NN / KT)   // 128
#define THREADS 512

#define KSTR 36         // K planes [m][d] stride (words)
#define PSTR 36         // P [r][m] stride
#define QLSTR 36        // qlo [r][d] stride
#define VSTR 264        // V [m][c] stride

// ---------------- global scratch ----------------
__device__ float g_qh[BB * NN * DQK];   // Q tf32-hi [b][n][d]
__device__ float g_ql[BB * NN * DQK];   // Q tf32-lo
__device__ float g_kh[BB * NN * DQK];   // K tf32-hi [b][m][d]
__device__ float g_kl[BB * NN * DQK];   // K tf32-lo
__device__ float g_v [BB * NN * CC];    // V tf32-rounded [b][m][c]

// ---------------- helpers ----------------
__device__ __forceinline__ uint32_t f2tf32(float f) {
    uint32_t u; asm("cvt.rna.tf32.f32 %0, %1;" : "=r"(u) : "f"(f)); return u;
}
__device__ __forceinline__ uint32_t smem_u32(const void* p) {
    uint32_t a;
    asm("{ .reg .u64 t; cvta.to.shared.u64 t, %1; cvt.u32.u64 %0, t; }" : "=r"(a) : "l"(p));
    return a;
}
__device__ __forceinline__ void cp16(uint32_t dst, const float* src) {
    asm volatile("cp.async.cg.shared.global [%0], [%1], 16;" :: "r"(dst), "l"(src));
}
#define CP_COMMIT() asm volatile("cp.async.commit_group;" ::: "memory")
#define CP_WAIT0()  asm volatile("cp.async.wait_group 0;" ::: "memory")

__device__ __forceinline__ void mma_tf32(float d[4],
    uint32_t a0, uint32_t a1, uint32_t a2, uint32_t a3,
    uint32_t b0, uint32_t b1)
{
    asm volatile(
        "mma.sync.aligned.m16n8k8.row.col.f32.tf32.tf32.f32 "
        "{%0,%1,%2,%3},{%4,%5,%6,%7},{%8,%9},{%0,%1,%2,%3};"
        : "+f"(d[0]), "+f"(d[1]), "+f"(d[2]), "+f"(d[3])
        : "r"(a0), "r"(a1), "r"(a2), "r"(a3), "r"(b0), "r"(b1));
}

// ---------------- smem layout (float offsets) ----------------
#define OFF_QLO  0                                    // 128*36 = 4608
#define OFF_KH(bf) (4608 + (bf) * 2304)               // per buf: Kh 1152 + Kl 1152
#define OFF_KL(bf) (4608 + (bf) * 2304 + 1152)
#define OFF_P(bf)  (9216 + (bf) * 4608)               // 128*36
#define OFF_V(bf)  (18432 + (bf) * 8448)              // 32*264
#define OFF_LSUM   35328                              // 2*128
#define SMEM_FLOATS 35584                             // 142336 bytes

// ---------------------------------------------------------------------------
// proj_qk: hi/lo tf32 split planes [b][n][32]
// ---------------------------------------------------------------------------
__global__ __launch_bounds__(256) void proj_qk(
    const float* __restrict__ X, const float* __restrict__ W,
    const float* __restrict__ bias,
    float* __restrict__ o_hi, float* __restrict__ o_lo)
{
    const int b  = blockIdx.z;
    const int n0 = blockIdx.x * 128;
    const int t  = threadIdx.x;
    const int tx = t & 31;
    const int ty = t >> 5;

    __shared__ float As[32][128];
    __shared__ float Bs[32][32];

    float acc[4][4];
#pragma unroll
    for (int i = 0; i < 4; i++)
#pragma unroll
        for (int u = 0; u < 4; u++) acc[i][u] = 0.f;

    const float* Xb = X + b * CC * NN;
    for (int c0 = 0; c0 < CC; c0 += 32) {
#pragma unroll
        for (int i = 0; i < 4; i++) {
            int idx = t + 256 * i;
            int cc  = idx >> 5;
            int nn  = (idx & 31) * 4;
            *(float4*)&As[cc][nn] = *(const float4*)(Xb + (c0 + cc) * NN + n0 + nn);
        }
        {
            int jj = t >> 3;
            int c4 = (t & 7) * 4;
            *(float4*)&Bs[jj][c4] = *(const float4*)(W + jj * CC + c0 + c4);
        }
        __syncthreads();
#pragma unroll
        for (int cc = 0; cc < 32; cc++) {
            float4 a = *(const float4*)&As[cc][tx * 4];
            float b0 = Bs[ty * 4 + 0][cc];
            float b1 = Bs[ty * 4 + 1][cc];
            float b2 = Bs[ty * 4 + 2][cc];
            float b3 = Bs[ty * 4 + 3][cc];
            acc[0][0] += a.x * b0; acc[0][1] += a.x * b1; acc[0][2] += a.x * b2; acc[0][3] += a.x * b3;
            acc[1][0] += a.y * b0; acc[1][1] += a.y * b1; acc[1][2] += a.y * b2; acc[1][3] += a.y * b3;
            acc[2][0] += a.z * b0; acc[2][1] += a.z * b1; acc[2][2] += a.z * b2; acc[2][3] += a.z * b3;
            acc[3][0] += a.w * b0; acc[3][1] += a.w * b1; acc[3][2] += a.w * b2; acc[3][3] += a.w * b3;
        }
        __syncthreads();
    }

    float bj[4] = { bias[ty*4], bias[ty*4+1], bias[ty*4+2], bias[ty*4+3] };
#pragma unroll
    for (int i = 0; i < 4; i++) {
        int n = n0 + tx * 4 + i;
        uint4 hi, lo;
        float v0 = acc[i][0] + bj[0];
        float v1 = acc[i][1] + bj[1];
        float v2 = acc[i][2] + bj[2];
        float v3 = acc[i][3] + bj[3];
        hi.x = f2tf32(v0); lo.x = f2tf32(v0 - __uint_as_float(hi.x));
        hi.y = f2tf32(v1); lo.y = f2tf32(v1 - __uint_as_float(hi.y));
        hi.z = f2tf32(v2); lo.z = f2tf32(v2 - __uint_as_float(hi.z));
        hi.w = f2tf32(v3); lo.w = f2tf32(v3 - __uint_as_float(hi.w));
        *(uint4*)(o_hi + ((size_t)b * NN + n) * DQK + ty * 4) = hi;
        *(uint4*)(o_lo + ((size_t)b * NN + n) * DQK + ty * 4) = lo;
    }
}

// ---------------------------------------------------------------------------
// proj_v: V projection, tf32-rounded, row-major [b][n][256]
// ---------------------------------------------------------------------------
__global__ __launch_bounds__(256) void proj_v(
    const float* __restrict__ X, const float* __restrict__ W,
    const float* __restrict__ bias, float* __restrict__ outv)
{
    const int b  = blockIdx.z;
    const int n0 = blockIdx.x * 128;
    const int j0 = blockIdx.y * 32;
    const int t  = threadIdx.x;
    const int tx = t & 31;
    const int ty = t >> 5;

    __shared__ float As[32][128];
    __shared__ float Bs[32][32];

    float acc[4][4];
#pragma unroll
    for (int i = 0; i < 4; i++)
#pragma unroll
        for (int u = 0; u < 4; u++) acc[i][u] = 0.f;

    const float* Xb = X + b * CC * NN;
    for (int c0 = 0; c0 < CC; c0 += 32) {
#pragma unroll
        for (int i = 0; i < 4; i++) {
            int idx = t + 256 * i;
            int cc  = idx >> 5;
            int nn  = (idx & 31) * 4;
            *(float4*)&As[cc][nn] = *(const float4*)(Xb + (c0 + cc) * NN + n0 + nn);
        }
        {
            int jj = t >> 3;
            int c4 = (t & 7) * 4;
            *(float4*)&Bs[jj][c4] = *(const float4*)(W + (j0 + jj) * CC + c0 + c4);
        }
        __syncthreads();
#pragma unroll
        for (int cc = 0; cc < 32; cc++) {
            float4 a = *(const float4*)&As[cc][tx * 4];
            float b0 = Bs[ty * 4 + 0][cc];
            float b1 = Bs[ty * 4 + 1][cc];
            float b2 = Bs[ty * 4 + 2][cc];
            float b3 = Bs[ty * 4 + 3][cc];
            acc[0][0] += a.x * b0; acc[0][1] += a.x * b1; acc[0][2] += a.x * b2; acc[0][3] += a.x * b3;
            acc[1][0] += a.y * b0; acc[1][1] += a.y * b1; acc[1][2] += a.y * b2; acc[1][3] += a.y * b3;
            acc[2][0] += a.z * b0; acc[2][1] += a.z * b1; acc[2][2] += a.z * b2; acc[2][3] += a.z * b3;
            acc[3][0] += a.w * b0; acc[3][1] += a.w * b1; acc[3][2] += a.w * b2; acc[3][3] += a.w * b3;
        }
        __syncthreads();
    }

    float bj[4] = { bias[j0+ty*4], bias[j0+ty*4+1], bias[j0+ty*4+2], bias[j0+ty*4+3] };
#pragma unroll
    for (int i = 0; i < 4; i++) {
        int n = n0 + tx * 4 + i;
        uint4 r;
        r.x = f2tf32(acc[i][0] + bj[0]);
        r.y = f2tf32(acc[i][1] + bj[1]);
        r.z = f2tf32(acc[i][2] + bj[2]);
        r.w = f2tf32(acc[i][3] + bj[3]);
        *(uint4*)(outv + ((size_t)b * NN + n) * CC + j0 + ty * 4) = r;
    }
}

// ---------------------------------------------------------------------------
// Flash attention: 128 queries/CTA, 512 threads (16 warps), 32-key tiles.
//   S = split-tf32 3-pass mma (qhi regs, qlo smem, K hi/lo smem [m][d]).
//   Warp w: S rows ms=(w&7)*16, keys nh=(w>>3)*16. PV channels cb=w*16.
//   P = exp(S) on C-frags, per-thread row-sum partials, reduced once.
//   K/V staged by cp.async, double-buffered. V reads = conflict-free LDS.
// ---------------------------------------------------------------------------
__global__ __launch_bounds__(THREADS) void flash_kernel(float* __restrict__ out)
{
    extern __shared__ float sm[];
    const uint32_t smem = smem_u32(sm);

    const int b    = blockIdx.y;
    const int n0   = blockIdx.x * TQ;
    const int t    = threadIdx.x;
    const int w    = t >> 5;
    const int lane = t & 31;
    const int gid  = lane >> 2;
    const int tid  = lane & 3;
    const int ms = (w & 7) * 16;
    const int nh = (w >> 3) * 16;
    const int cb = w * 16;

    const float* gqh = g_qh + ((size_t)b * NN + n0) * DQK;
    const float* gql = g_ql + ((size_t)b * NN + n0) * DQK;
    const float* gkh = g_kh + (size_t)b * NN * DQK;
    const float* gkl = g_kl + (size_t)b * NN * DQK;
    const float* gv  = g_v  + (size_t)b * NN * CC;

    float*    Qlo  = sm + OFF_QLO;
    float*    lsum = sm + OFF_LSUM;
    uint32_t* Pb[2] = { (uint32_t*)(sm + OFF_P(0)), (uint32_t*)(sm + OFF_P(1)) };
    uint32_t* Vb[2] = { (uint32_t*)(sm + OFF_V(0)), (uint32_t*)(sm + OFF_V(1)) };
    uint32_t* Khb[2] = { (uint32_t*)(sm + OFF_KH(0)), (uint32_t*)(sm + OFF_KH(1)) };
    uint32_t* Klb[2] = { (uint32_t*)(sm + OFF_KL(0)), (uint32_t*)(sm + OFF_KL(1)) };

    // --- Q fragments: qhi regs (all warps), qlo -> smem (warps 0-7 only) ---
    uint32_t qhi[4][4];
    {
        const float* q0 = gqh + (size_t)(ms + gid) * DQK;
        const float* q1 = q0 + 8 * DQK;
        const float* l0 = gql + (size_t)(ms + gid) * DQK;
        const float* l1 = l0 + 8 * DQK;
#pragma unroll
        for (int kk = 0; kk < 4; kk++) {
            qhi[kk][0] = __float_as_uint(__ldg(q0 + kk * 8 + tid));
            qhi[kk][1] = __float_as_uint(__ldg(q1 + kk * 8 + tid));
            qhi[kk][2] = __float_as_uint(__ldg(q0 + kk * 8 + tid + 4));
            qhi[kk][3] = __float_as_uint(__ldg(q1 + kk * 8 + tid + 4));
            if (w < 8) {
                Qlo[(ms + gid)     * QLSTR + kk * 8 + tid]     = __ldg(l0 + kk * 8 + tid);
                Qlo[(ms + gid + 8) * QLSTR + kk * 8 + tid]     = __ldg(l1 + kk * 8 + tid);
                Qlo[(ms + gid)     * QLSTR + kk * 8 + tid + 4] = __ldg(l0 + kk * 8 + tid + 4);
                Qlo[(ms + gid + 8) * QLSTR + kk * 8 + tid + 4] = __ldg(l1 + kk * 8 + tid + 4);
            }
        }
    }

    float acc[8][2][4];
#pragma unroll
    for (int it = 0; it < 8; it++)
#pragma unroll
        for (int jt = 0; jt < 2; jt++)
#pragma unroll
            for (int u = 0; u < 4; u++) acc[it][jt][u] = 0.f;

    float lrun_lo = 0.f, lrun_hi = 0.f;

    // --- cp.async staging lambdas ---
    auto stage_k = [&](int kt_idx, int bf) {
        // 512 chunks: plane = t>>8, m = (t>>3)&31, c = t&7
        const int plane = t >> 8;
        const int m = (t >> 3) & 31;
        const int c = t & 7;
        const float* src = (plane ? gkl : gkh) + (size_t)(kt_idx * KT + m) * DQK + c * 4;
        const uint32_t base = plane ? (smem + OFF_KL(bf) * 4) : (smem + OFF_KH(bf) * 4);
        cp16(base + (m * KSTR + c * 4) * 4, src);
    };
    auto stage_v = [&](int kt_idx, int bf) {
        const uint32_t base = smem + OFF_V(bf) * 4;
#pragma unroll
        for (int i = 0; i < 4; i++) {
            int ch = t + THREADS * i;           // 0..2047
            int m  = ch >> 6;
            int c4 = (ch & 63) * 4;
            cp16(base + (m * VSTR + c4) * 4, gv + (size_t)(kt_idx * KT + m) * CC + c4);
        }
    };

    // --- S phase ---
    auto s_phase = [&](const uint32_t* Kh, const uint32_t* Kl, uint32_t* Pw) {
        float sf[2][4];
#pragma unroll
        for (int j = 0; j < 2; j++)
#pragma unroll
            for (int u = 0; u < 4; u++) sf[j][u] = 0.f;

#pragma unroll
        for (int kk = 0; kk < 4; kk++) {
            uint32_t ql0 = __float_as_uint(Qlo[(ms + gid)     * QLSTR + kk * 8 + tid]);
            uint32_t ql1 = __float_as_uint(Qlo[(ms + gid + 8) * QLSTR + kk * 8 + tid]);
            uint32_t ql2 = __float_as_uint(Qlo[(ms + gid)     * QLSTR + kk * 8 + tid + 4]);
            uint32_t ql3 = __float_as_uint(Qlo[(ms + gid + 8) * QLSTR + kk * 8 + tid + 4]);
#pragma unroll
            for (int j = 0; j < 2; j++) {
                const int cn = nh + 8 * j + gid;
                uint32_t bh0 = Kh[cn * KSTR + kk * 8 + tid];
                uint32_t bh1 = Kh[cn * KSTR + kk * 8 + tid + 4];
                uint32_t bl0 = Kl[cn * KSTR + kk * 8 + tid];
                uint32_t bl1 = Kl[cn * KSTR + kk * 8 + tid + 4];
                mma_tf32(sf[j], qhi[kk][0], qhi[kk][1], qhi[kk][2], qhi[kk][3], bh0, bh1);
                mma_tf32(sf[j], ql0, ql1, ql2, ql3, bh0, bh1);
                mma_tf32(sf[j], qhi[kk][0], qhi[kk][1], qhi[kk][2], qhi[kk][3], bl0, bl1);
            }
        }

#pragma unroll
        for (int j = 0; j < 2; j++) {
            float e0 = __expf(sf[j][0]);
            float e1 = __expf(sf[j][1]);
            float e2 = __expf(sf[j][2]);
            float e3 = __expf(sf[j][3]);
            lrun_lo += e0 + e1;
            lrun_hi += e2 + e3;
            uint2 plo, phi;
            plo.x = f2tf32(e0); plo.y = f2tf32(e1);
            phi.x = f2tf32(e2); phi.y = f2tf32(e3);
            const int cw = nh + 8 * j + 2 * tid;
            *(uint2*)&Pw[(ms + gid)     * PSTR + cw] = plo;
            *(uint2*)&Pw[(ms + gid + 8) * PSTR + cw] = phi;
        }
    };

    // --- PV phase ---
    auto pv_phase = [&](const uint32_t* P, const uint32_t* V) {
#pragma unroll
        for (int ks = 0; ks < 4; ks++) {
            const int m0 = ks * 8;
            uint32_t b0[2], b1[2];
#pragma unroll
            for (int jt = 0; jt < 2; jt++) {
                b0[jt] = V[(m0 + tid)     * VSTR + cb + jt * 8 + gid];
                b1[jt] = V[(m0 + tid + 4) * VSTR + cb + jt * 8 + gid];
            }
#pragma unroll
            for (int it = 0; it < 8; it++) {
                uint32_t a0 = P[(it * 16 + gid)     * PSTR + m0 + tid];
                uint32_t a1 = P[(it * 16 + gid + 8) * PSTR + m0 + tid];
                uint32_t a2 = P[(it * 16 + gid)     * PSTR + m0 + tid + 4];
                uint32_t a3 = P[(it * 16 + gid + 8) * PSTR + m0 + tid + 4];
#pragma unroll
                for (int jt = 0; jt < 2; jt++)
                    mma_tf32(acc[it][jt], a0, a1, a2, a3, b0[jt], b1[jt]);
            }
        }
    };

    // --- prologue: K(0)->K[0], K(1)->K[1], V(0)->V[0] ---
    stage_k(0, 0);
    stage_k(1, 1);
    stage_v(0, 0);
    CP_COMMIT();
    CP_WAIT0();
    __syncthreads();
    s_phase(Khb[0], Klb[0], Pb[0]);
    __syncthreads();

    // --- main loop ---
    for (int kt = 0; kt < NKT; kt++) {
        const int buf = kt & 1;

        if (kt + 2 < NKT) stage_k(kt + 2, buf);
        if (kt + 1 < NKT) stage_v(kt + 1, buf ^ 1);
        CP_COMMIT();

        pv_phase(Pb[buf], Vb[buf]);

        if (kt + 1 < NKT) s_phase(Khb[buf ^ 1], Klb[buf ^ 1], Pb[buf ^ 1]);

        CP_WAIT0();
        __syncthreads();
    }

    // --- row-sum reduction ---
    lrun_lo += __shfl_xor_sync(0xffffffffu, lrun_lo, 1);
    lrun_lo += __shfl_xor_sync(0xffffffffu, lrun_lo, 2);
    lrun_hi += __shfl_xor_sync(0xffffffffu, lrun_hi, 1);
    lrun_hi += __shfl_xor_sync(0xffffffffu, lrun_hi, 2);
    if (tid == 0) {
        lsum[(w >> 3) * 128 + ms + gid]     = lrun_lo;
        lsum[(w >> 3) * 128 + ms + gid + 8] = lrun_hi;
    }
    __syncthreads();
    if (t < 128) Qlo[t] = 1.f / (lsum[t] + lsum[128 + t]);   // reuse Qlo as inv
    __syncthreads();

    // --- epilogue: out[b][c][n0+r] ---
    float* ob = out + (size_t)b * CC * NN + n0;
#pragma unroll
    for (int it = 0; it < 8; it++) {
        const int r_lo = it * 16 + gid;
        const int r_hi = r_lo + 8;
        const float ilo = Qlo[r_lo];
        const float ihi = Qlo[r_hi];
#pragma unroll
        for (int jt = 0; jt < 2; jt++) {
            const int c0 = cb + jt * 8 + tid * 2;
            ob[(size_t)(c0    ) * NN + r_lo] = acc[it][jt][0] * ilo;
            ob[(size_t)(c0 + 1) * NN + r_lo] = acc[it][jt][1] * ilo;
            ob[(size_t)(c0    ) * NN + r_hi] = acc[it][jt][2] * ihi;
            ob[(size_t)(c0 + 1) * NN + r_hi] = acc[it][jt][3] * ihi;
        }
    }
}

// ---------------------------------------------------------------------------
extern "C" void kernel_launch(void* const* d_in, const int* in_sizes, int n_in,
                              void* d_out, int out_size)
{
    const float* f1 = (const float*)d_in[0];
    const float* f2 = (const float*)d_in[1];
    const float* Wq = (const float*)d_in[2];
    const float* bq = (const float*)d_in[3];
    const float* Wk = (const float*)d_in[4];
    const float* bk = (const float*)d_in[5];
    const float* Wv = (const float*)d_in[6];
    const float* bv = (const float*)d_in[7];
    float* out = (float*)d_out;

    float *qh, *ql, *kh, *kl, *vp;
    cudaGetSymbolAddress((void**)&qh, g_qh);
    cudaGetSymbolAddress((void**)&ql, g_ql);
    cudaGetSymbolAddress((void**)&kh, g_kh);
    cudaGetSymbolAddress((void**)&kl, g_kl);
    cudaGetSymbolAddress((void**)&vp, g_v);

    const int smem_bytes = SMEM_FLOATS * (int)sizeof(float);
    cudaFuncSetAttribute(flash_kernel,
                         cudaFuncAttributeMaxDynamicSharedMemorySize, smem_bytes);

    proj_qk<<<dim3(NN / 128, 1, BB), 256>>>(f1, Wq, bq, qh, ql);
    proj_qk<<<dim3(NN / 128, 1, BB), 256>>>(f2, Wk, bk, kh, kl);
    proj_v <<<dim3(NN / 128, 8, BB), 256>>>(f2, Wv, bv, vp);
    flash_kernel<<<dim3(NN / TQ, BB), THREADS, smem_bytes>>>(out);
}

// round 14
// speedup vs baseline: 1.1698x; 1.1698x over previous
#include <cuda_runtime.h>
#include <stdint.h>

#define BB 4
#define CC 256
#define DQK 32
#define NN 4096
#define TQ 128          // queries per CTA
#define KT 32           // keys per tile
#define NKT (NN / KT)   // 128
#define THREADS 512

#define KSTR 36         // K planes [m][d] stride (words)
#define PSTR 36         // P [r][m] stride
#define QLSTR 36        // qlo [r][d] stride
#define VSTR 264        // V [m][c] stride

// ---------------- global scratch ----------------
__device__ float g_qh[BB * NN * DQK];   // Q tf32-hi [b][n][d]
__device__ float g_ql[BB * NN * DQK];   // Q tf32-lo
__device__ float g_kh[BB * NN * DQK];   // K tf32-hi [b][m][d]
__device__ float g_kl[BB * NN * DQK];   // K tf32-lo
__device__ float g_v [BB * NN * CC];    // V tf32-rounded [b][m][c]

// ---------------- helpers ----------------
__device__ __forceinline__ uint32_t f2tf32(float f) {
    uint32_t u; asm("cvt.rna.tf32.f32 %0, %1;" : "=r"(u) : "f"(f)); return u;
}
__device__ __forceinline__ uint32_t smem_u32(const void* p) {
    uint32_t a;
    asm("{ .reg .u64 t; cvta.to.shared.u64 t, %1; cvt.u32.u64 %0, t; }" : "=r"(a) : "l"(p));
    return a;
}
__device__ __forceinline__ void cp16(uint32_t dst, const float* src) {
    asm volatile("cp.async.cg.shared.global [%0], [%1], 16;" :: "r"(dst), "l"(src));
}
#define CP_COMMIT() asm volatile("cp.async.commit_group;" ::: "memory")
#define CP_WAIT0()  asm volatile("cp.async.wait_group 0;" ::: "memory")
#define CP_WAIT1()  asm volatile("cp.async.wait_group 1;" ::: "memory")

__device__ __forceinline__ void mma_tf32(float d[4],
    uint32_t a0, uint32_t a1, uint32_t a2, uint32_t a3,
    uint32_t b0, uint32_t b1)
{
    asm volatile(
        "mma.sync.aligned.m16n8k8.row.col.f32.tf32.tf32.f32 "
        "{%0,%1,%2,%3},{%4,%5,%6,%7},{%8,%9},{%0,%1,%2,%3};"
        : "+f"(d[0]), "+f"(d[1]), "+f"(d[2]), "+f"(d[3])
        : "r"(a0), "r"(a1), "r"(a2), "r"(a3), "r"(b0), "r"(b1));
}

// ---------------- smem layout (float offsets) ----------------
#define OFF_QLO  0                                    // 128*36 = 4608
#define OFF_KH(bf) (4608 + (bf) * 2304)               // per buf: Kh 1152 + Kl 1152
#define OFF_KL(bf) (4608 + (bf) * 2304 + 1152)
#define OFF_P(bf)  (9216 + (bf) * 4608)               // 128*36
#define OFF_V(bf)  (18432 + (bf) * 8448)              // 32*264, 3 buffers
#define OFF_LSUM   43776                              // 2*128
#define SMEM_FLOATS 44032                             // 176128 bytes

// ---------------------------------------------------------------------------
// proj_qk: hi/lo tf32 split planes [b][n][32]
// ---------------------------------------------------------------------------
__global__ __launch_bounds__(256) void proj_qk(
    const float* __restrict__ X, const float* __restrict__ W,
    const float* __restrict__ bias,
    float* __restrict__ o_hi, float* __restrict__ o_lo)
{
    const int b  = blockIdx.z;
    const int n0 = blockIdx.x * 128;
    const int t  = threadIdx.x;
    const int tx = t & 31;
    const int ty = t >> 5;

    __shared__ float As[32][128];
    __shared__ float Bs[32][32];

    float acc[4][4];
#pragma unroll
    for (int i = 0; i < 4; i++)
#pragma unroll
        for (int u = 0; u < 4; u++) acc[i][u] = 0.f;

    const float* Xb = X + b * CC * NN;
    for (int c0 = 0; c0 < CC; c0 += 32) {
#pragma unroll
        for (int i = 0; i < 4; i++) {
            int idx = t + 256 * i;
            int cc  = idx >> 5;
            int nn  = (idx & 31) * 4;
            *(float4*)&As[cc][nn] = *(const float4*)(Xb + (c0 + cc) * NN + n0 + nn);
        }
        {
            int jj = t >> 3;
            int c4 = (t & 7) * 4;
            *(float4*)&Bs[jj][c4] = *(const float4*)(W + jj * CC + c0 + c4);
        }
        __syncthreads();
#pragma unroll
        for (int cc = 0; cc < 32; cc++) {
            float4 a = *(const float4*)&As[cc][tx * 4];
            float b0 = Bs[ty * 4 + 0][cc];
            float b1 = Bs[ty * 4 + 1][cc];
            float b2 = Bs[ty * 4 + 2][cc];
            float b3 = Bs[ty * 4 + 3][cc];
            acc[0][0] += a.x * b0; acc[0][1] += a.x * b1; acc[0][2] += a.x * b2; acc[0][3] += a.x * b3;
            acc[1][0] += a.y * b0; acc[1][1] += a.y * b1; acc[1][2] += a.y * b2; acc[1][3] += a.y * b3;
            acc[2][0] += a.z * b0; acc[2][1] += a.z * b1; acc[2][2] += a.z * b2; acc[2][3] += a.z * b3;
            acc[3][0] += a.w * b0; acc[3][1] += a.w * b1; acc[3][2] += a.w * b2; acc[3][3] += a.w * b3;
        }
        __syncthreads();
    }

    float bj[4] = { bias[ty*4], bias[ty*4+1], bias[ty*4+2], bias[ty*4+3] };
#pragma unroll
    for (int i = 0; i < 4; i++) {
        int n = n0 + tx * 4 + i;
        uint4 hi, lo;
        float v0 = acc[i][0] + bj[0];
        float v1 = acc[i][1] + bj[1];
        float v2 = acc[i][2] + bj[2];
        float v3 = acc[i][3] + bj[3];
        hi.x = f2tf32(v0); lo.x = f2tf32(v0 - __uint_as_float(hi.x));
        hi.y = f2tf32(v1); lo.y = f2tf32(v1 - __uint_as_float(hi.y));
        hi.z = f2tf32(v2); lo.z = f2tf32(v2 - __uint_as_float(hi.z));
        hi.w = f2tf32(v3); lo.w = f2tf32(v3 - __uint_as_float(hi.w));
        *(uint4*)(o_hi + ((size_t)b * NN + n) * DQK + ty * 4) = hi;
        *(uint4*)(o_lo + ((size_t)b * NN + n) * DQK + ty * 4) = lo;
    }
}

// ---------------------------------------------------------------------------
// proj_v: V projection, tf32-rounded, row-major [b][n][256]
// ---------------------------------------------------------------------------
__global__ __launch_bounds__(256) void proj_v(
    const float* __restrict__ X, const float* __restrict__ W,
    const float* __restrict__ bias, float* __restrict__ outv)
{
    const int b  = blockIdx.z;
    const int n0 = blockIdx.x * 128;
    const int j0 = blockIdx.y * 32;
    const int t  = threadIdx.x;
    const int tx = t & 31;
    const int ty = t >> 5;

    __shared__ float As[32][128];
    __shared__ float Bs[32][32];

    float acc[4][4];
#pragma unroll
    for (int i = 0; i < 4; i++)
#pragma unroll
        for (int u = 0; u < 4; u++) acc[i][u] = 0.f;

    const float* Xb = X + b * CC * NN;
    for (int c0 = 0; c0 < CC; c0 += 32) {
#pragma unroll
        for (int i = 0; i < 4; i++) {
            int idx = t + 256 * i;
            int cc  = idx >> 5;
            int nn  = (idx & 31) * 4;
            *(float4*)&As[cc][nn] = *(const float4*)(Xb + (c0 + cc) * NN + n0 + nn);
        }
        {
            int jj = t >> 3;
            int c4 = (t & 7) * 4;
            *(float4*)&Bs[jj][c4] = *(const float4*)(W + (j0 + jj) * CC + c0 + c4);
        }
        __syncthreads();
#pragma unroll
        for (int cc = 0; cc < 32; cc++) {
            float4 a = *(const float4*)&As[cc][tx * 4];
            float b0 = Bs[ty * 4 + 0][cc];
            float b1 = Bs[ty * 4 + 1][cc];
            float b2 = Bs[ty * 4 + 2][cc];
            float b3 = Bs[ty * 4 + 3][cc];
            acc[0][0] += a.x * b0; acc[0][1] += a.x * b1; acc[0][2] += a.x * b2; acc[0][3] += a.x * b3;
            acc[1][0] += a.y * b0; acc[1][1] += a.y * b1; acc[1][2] += a.y * b2; acc[1][3] += a.y * b3;
            acc[2][0] += a.z * b0; acc[2][1] += a.z * b1; acc[2][2] += a.z * b2; acc[2][3] += a.z * b3;
            acc[3][0] += a.w * b0; acc[3][1] += a.w * b1; acc[3][2] += a.w * b2; acc[3][3] += a.w * b3;
        }
        __syncthreads();
    }

    float bj[4] = { bias[j0+ty*4], bias[j0+ty*4+1], bias[j0+ty*4+2], bias[j0+ty*4+3] };
#pragma unroll
    for (int i = 0; i < 4; i++) {
        int n = n0 + tx * 4 + i;
        uint4 r;
        r.x = f2tf32(acc[i][0] + bj[0]);
        r.y = f2tf32(acc[i][1] + bj[1]);
        r.z = f2tf32(acc[i][2] + bj[2]);
        r.w = f2tf32(acc[i][3] + bj[3]);
        *(uint4*)(outv + ((size_t)b * NN + n) * CC + j0 + ty * 4) = r;
    }
}

// ---------------------------------------------------------------------------
// Flash attention: 128 q/CTA, 512 threads. PV retile: warp w covers
// rows rg=(w&1)*64, channels cg=(w>>1)*32 (halves P broadcast traffic).
// V triple-buffered, staged at distance 2 with cp.async.wait_group 1 so
// staging latency never gates the current iteration.
// Hazards: iter kt: stage{K(kt+2)->Kbuf[kt&1], V(kt+2)->Vbuf[(kt+2)%3]};
//   PV(kt) reads Vbuf[kt%3], P[kt&1]; WAIT1 ensures group(kt-1) done
//   (K(kt+1),V(kt+1)); s_phase(kt+1) reads Kbuf[(kt+1)&1], writes P[(kt+1)&1].
// ---------------------------------------------------------------------------
__global__ __launch_bounds__(THREADS) void flash_kernel(float* __restrict__ out)
{
    extern __shared__ float sm[];
    const uint32_t smem = smem_u32(sm);

    const int b    = blockIdx.y;
    const int n0   = blockIdx.x * TQ;
    const int t    = threadIdx.x;
    const int w    = t >> 5;
    const int lane = t & 31;
    const int gid  = lane >> 2;
    const int tid  = lane & 3;
    // S mapping (unchanged from R13)
    const int ms = (w & 7) * 16;
    const int nh = (w >> 3) * 16;
    // PV mapping: 64 rows x 32 channels per warp
    const int rg = (w & 1) * 64;
    const int cg = (w >> 1) * 32;

    const float* gqh = g_qh + ((size_t)b * NN + n0) * DQK;
    const float* gql = g_ql + ((size_t)b * NN + n0) * DQK;
    const float* gkh = g_kh + (size_t)b * NN * DQK;
    const float* gkl = g_kl + (size_t)b * NN * DQK;
    const float* gv  = g_v  + (size_t)b * NN * CC;

    float*    Qlo  = sm + OFF_QLO;
    float*    lsum = sm + OFF_LSUM;
    uint32_t* Pb[2]  = { (uint32_t*)(sm + OFF_P(0)), (uint32_t*)(sm + OFF_P(1)) };
    uint32_t* Vb[3]  = { (uint32_t*)(sm + OFF_V(0)), (uint32_t*)(sm + OFF_V(1)),
                         (uint32_t*)(sm + OFF_V(2)) };
    uint32_t* Khb[2] = { (uint32_t*)(sm + OFF_KH(0)), (uint32_t*)(sm + OFF_KH(1)) };
    uint32_t* Klb[2] = { (uint32_t*)(sm + OFF_KL(0)), (uint32_t*)(sm + OFF_KL(1)) };

    // --- Q fragments: qhi regs (all warps), qlo -> smem (warps 0-7) ---
    uint32_t qhi[4][4];
    {
        const float* q0 = gqh + (size_t)(ms + gid) * DQK;
        const float* q1 = q0 + 8 * DQK;
        const float* l0 = gql + (size_t)(ms + gid) * DQK;
        const float* l1 = l0 + 8 * DQK;
#pragma unroll
        for (int kk = 0; kk < 4; kk++) {
            qhi[kk][0] = __float_as_uint(__ldg(q0 + kk * 8 + tid));
            qhi[kk][1] = __float_as_uint(__ldg(q1 + kk * 8 + tid));
            qhi[kk][2] = __float_as_uint(__ldg(q0 + kk * 8 + tid + 4));
            qhi[kk][3] = __float_as_uint(__ldg(q1 + kk * 8 + tid + 4));
            if (w < 8) {
                Qlo[(ms + gid)     * QLSTR + kk * 8 + tid]     = __ldg(l0 + kk * 8 + tid);
                Qlo[(ms + gid + 8) * QLSTR + kk * 8 + tid]     = __ldg(l1 + kk * 8 + tid);
                Qlo[(ms + gid)     * QLSTR + kk * 8 + tid + 4] = __ldg(l0 + kk * 8 + tid + 4);
                Qlo[(ms + gid + 8) * QLSTR + kk * 8 + tid + 4] = __ldg(l1 + kk * 8 + tid + 4);
            }
        }
    }

    float acc[4][4][4];
#pragma unroll
    for (int it = 0; it < 4; it++)
#pragma unroll
        for (int jt = 0; jt < 4; jt++)
#pragma unroll
            for (int u = 0; u < 4; u++) acc[it][jt][u] = 0.f;

    float lrun_lo = 0.f, lrun_hi = 0.f;

    auto stage_k = [&](int kt_idx, int bf) {
        const int plane = t >> 8;
        const int m = (t >> 3) & 31;
        const int c = t & 7;
        const float* src = (plane ? gkl : gkh) + (size_t)(kt_idx * KT + m) * DQK + c * 4;
        const uint32_t base = plane ? (smem + OFF_KL(bf) * 4) : (smem + OFF_KH(bf) * 4);
        cp16(base + (m * KSTR + c * 4) * 4, src);
    };
    auto stage_v = [&](int kt_idx, int bf) {
        const uint32_t base = smem + OFF_V(bf) * 4;
#pragma unroll
        for (int i = 0; i < 4; i++) {
            int ch = t + THREADS * i;
            int m  = ch >> 6;
            int c4 = (ch & 63) * 4;
            cp16(base + (m * VSTR + c4) * 4, gv + (size_t)(kt_idx * KT + m) * CC + c4);
        }
    };

    auto s_phase = [&](const uint32_t* Kh, const uint32_t* Kl, uint32_t* Pw) {
        float sf[2][4];
#pragma unroll
        for (int j = 0; j < 2; j++)
#pragma unroll
            for (int u = 0; u < 4; u++) sf[j][u] = 0.f;

#pragma unroll
        for (int kk = 0; kk < 4; kk++) {
            uint32_t ql0 = __float_as_uint(Qlo[(ms + gid)     * QLSTR + kk * 8 + tid]);
            uint32_t ql1 = __float_as_uint(Qlo[(ms + gid + 8) * QLSTR + kk * 8 + tid]);
            uint32_t ql2 = __float_as_uint(Qlo[(ms + gid)     * QLSTR + kk * 8 + tid + 4]);
            uint32_t ql3 = __float_as_uint(Qlo[(ms + gid + 8) * QLSTR + kk * 8 + tid + 4]);
#pragma unroll
            for (int j = 0; j < 2; j++) {
                const int cn = nh + 8 * j + gid;
                uint32_t bh0 = Kh[cn * KSTR + kk * 8 + tid];
                uint32_t bh1 = Kh[cn * KSTR + kk * 8 + tid + 4];
                uint32_t bl0 = Kl[cn * KSTR + kk * 8 + tid];
                uint32_t bl1 = Kl[cn * KSTR + kk * 8 + tid + 4];
                mma_tf32(sf[j], qhi[kk][0], qhi[kk][1], qhi[kk][2], qhi[kk][3], bh0, bh1);
                mma_tf32(sf[j], ql0, ql1, ql2, ql3, bh0, bh1);
                mma_tf32(sf[j], qhi[kk][0], qhi[kk][1], qhi[kk][2], qhi[kk][3], bl0, bl1);
            }
        }

#pragma unroll
        for (int j = 0; j < 2; j++) {
            float e0 = __expf(sf[j][0]);
            float e1 = __expf(sf[j][1]);
            float e2 = __expf(sf[j][2]);
            float e3 = __expf(sf[j][3]);
            lrun_lo += e0 + e1;
            lrun_hi += e2 + e3;
            uint2 plo, phi;
            plo.x = f2tf32(e0); plo.y = f2tf32(e1);
            phi.x = f2tf32(e2); phi.y = f2tf32(e3);
            const int cw = nh + 8 * j + 2 * tid;
            *(uint2*)&Pw[(ms + gid)     * PSTR + cw] = plo;
            *(uint2*)&Pw[(ms + gid + 8) * PSTR + cw] = phi;
        }
    };

    auto pv_phase = [&](const uint32_t* P, const uint32_t* V) {
#pragma unroll
        for (int ks = 0; ks < 4; ks++) {
            const int m0 = ks * 8;
            uint32_t b0[4], b1[4];
#pragma unroll
            for (int jt = 0; jt < 4; jt++) {
                b0[jt] = V[(m0 + tid)     * VSTR + cg + jt * 8 + gid];
                b1[jt] = V[(m0 + tid + 4) * VSTR + cg + jt * 8 + gid];
            }
#pragma unroll
            for (int it = 0; it < 4; it++) {
                const int r0 = rg + it * 16 + gid;
                uint32_t a0 = P[(r0    ) * PSTR + m0 + tid];
                uint32_t a1 = P[(r0 + 8) * PSTR + m0 + tid];
                uint32_t a2 = P[(r0    ) * PSTR + m0 + tid + 4];
                uint32_t a3 = P[(r0 + 8) * PSTR + m0 + tid + 4];
#pragma unroll
                for (int jt = 0; jt < 4; jt++)
                    mma_tf32(acc[it][jt], a0, a1, a2, a3, b0[jt], b1[jt]);
            }
        }
    };

    // --- prologue: K(0),K(1),V(0),V(1) staged & complete; S(0)->P0 ---
    stage_k(0, 0);
    stage_k(1, 1);
    stage_v(0, 0);
    stage_v(1, 1);
    CP_COMMIT();
    CP_WAIT0();
    __syncthreads();
    s_phase(Khb[0], Klb[0], Pb[0]);
    __syncthreads();

    // --- main loop ---
    int v_rd = 0, v_wr = 2;
    for (int kt = 0; kt < NKT; kt++) {
        const int buf = kt & 1;

        if (kt + 2 < NKT) {
            stage_k(kt + 2, buf);        // K(kt+2) -> buf (kt+2)&1 == kt&1
            stage_v(kt + 2, v_wr);
        }
        CP_COMMIT();

        pv_phase(Pb[buf], Vb[v_rd]);

        CP_WAIT1();                      // group(kt-1) done: K(kt+1), V(kt+1)

        if (kt + 1 < NKT)
            s_phase(Khb[buf ^ 1], Klb[buf ^ 1], Pb[buf ^ 1]);

        __syncthreads();
        v_rd = (v_rd == 2) ? 0 : v_rd + 1;
        v_wr = (v_wr == 2) ? 0 : v_wr + 1;
    }

    // --- row-sum reduction ---
    lrun_lo += __shfl_xor_sync(0xffffffffu, lrun_lo, 1);
    lrun_lo += __shfl_xor_sync(0xffffffffu, lrun_lo, 2);
    lrun_hi += __shfl_xor_sync(0xffffffffu, lrun_hi, 1);
    lrun_hi += __shfl_xor_sync(0xffffffffu, lrun_hi, 2);
    if (tid == 0) {
        lsum[(w >> 3) * 128 + ms + gid]     = lrun_lo;
        lsum[(w >> 3) * 128 + ms + gid + 8] = lrun_hi;
    }
    __syncthreads();
    if (t < 128) Qlo[t] = 1.f / (lsum[t] + lsum[128 + t]);   // reuse Qlo as inv
    __syncthreads();

    // --- epilogue: out[b][c][n0+r] ---
    float* ob = out + (size_t)b * CC * NN + n0;
#pragma unroll
    for (int it = 0; it < 4; it++) {
        const int r_lo = rg + it * 16 + gid;
        const int r_hi = r_lo + 8;
        const float ilo = Qlo[r_lo];
        const float ihi = Qlo[r_hi];
#pragma unroll
        for (int jt = 0; jt < 4; jt++) {
            const int c0 = cg + jt * 8 + tid * 2;
            ob[(size_t)(c0    ) * NN + r_lo] = acc[it][jt][0] * ilo;
            ob[(size_t)(c0 + 1) * NN + r_lo] = acc[it][jt][1] * ilo;
            ob[(size_t)(c0    ) * NN + r_hi] = acc[it][jt][2] * ihi;
            ob[(size_t)(c0 + 1) * NN + r_hi] = acc[it][jt][3] * ihi;
        }
    }
}

// ---------------------------------------------------------------------------
extern "C" void kernel_launch(void* const* d_in, const int* in_sizes, int n_in,
                              void* d_out, int out_size)
{
    const float* f1 = (const float*)d_in[0];
    const float* f2 = (const float*)d_in[1];
    const float* Wq = (const float*)d_in[2];
    const float* bq = (const float*)d_in[3];
    const float* Wk = (const float*)d_in[4];
    const float* bk = (const float*)d_in[5];
    const float* Wv = (const float*)d_in[6];
    const float* bv = (const float*)d_in[7];
    float* out = (float*)d_out;

    float *qh, *ql, *kh, *kl, *vp;
    cudaGetSymbolAddress((void**)&qh, g_qh);
    cudaGetSymbolAddress((void**)&ql, g_ql);
    cudaGetSymbolAddress((void**)&kh, g_kh);
    cudaGetSymbolAddress((void**)&kl, g_kl);
    cudaGetSymbolAddress((void**)&vp, g_v);

    const int smem_bytes = SMEM_FLOATS * (int)sizeof(float);
    cudaFuncSetAttribute(flash_kernel,
                         cudaFuncAttributeMaxDynamicSharedMemorySize, smem_bytes);

    proj_qk<<<dim3(NN / 128, 1, BB), 256>>>(f1, Wq, bq, qh, ql);
    proj_qk<<<dim3(NN / 128, 1, BB), 256>>>(f2, Wk, bk, kh, kl);
    proj_v <<<dim3(NN / 128, 8, BB), 256>>>(f2, Wv, bv, vp);
    flash_kernel<<<dim3(NN / TQ, BB), THREADS, smem_bytes>>>(out);
}

// round 15
// speedup vs baseline: 1.2611x; 1.0781x over previous
#include <cuda_runtime.h>
#include <stdint.h>

#define BB 4
#define CC 256
#define DQK 32
#define NN 4096
#define TQ 128          // queries per CTA
#define KT 32           // keys per tile
#define NKT (NN / KT)   // 128
#define THREADS 512

#define KSTR 36         // K planes [m][d] stride (words)
#define QLSTR 36
#define VSTR 264        // V [m][c] stride

// ---------------- global scratch ----------------
__device__ float g_qh[BB * NN * DQK];   // Q tf32-hi [b][n][d]
__device__ float g_ql[BB * NN * DQK];   // Q tf32-lo
__device__ float g_kh[BB * NN * DQK];   // K tf32-hi [b][m][d]
__device__ float g_kl[BB * NN * DQK];   // K tf32-lo
__device__ float g_v [BB * NN * CC];    // V tf32-rounded [b][m][c]

// ---------------- helpers ----------------
__device__ __forceinline__ uint32_t f2tf32(float f) {
    uint32_t u; asm("cvt.rna.tf32.f32 %0, %1;" : "=r"(u) : "f"(f)); return u;
}
__device__ __forceinline__ uint32_t smem_u32(const void* p) {
    uint32_t a;
    asm("{ .reg .u64 t; cvta.to.shared.u64 t, %1; cvt.u32.u64 %0, t; }" : "=r"(a) : "l"(p));
    return a;
}
__device__ __forceinline__ void cp16(uint32_t dst, const float* src) {
    asm volatile("cp.async.cg.shared.global [%0], [%1], 16;" :: "r"(dst), "l"(src));
}
#define CP_COMMIT() asm volatile("cp.async.commit_group;" ::: "memory")
#define CP_WAIT0()  asm volatile("cp.async.wait_group 0;" ::: "memory")
#define CP_WAIT1()  asm volatile("cp.async.wait_group 1;" ::: "memory")

__device__ __forceinline__ void mma_tf32(float d[4],
    uint32_t a0, uint32_t a1, uint32_t a2, uint32_t a3,
    uint32_t b0, uint32_t b1)
{
    asm volatile(
        "mma.sync.aligned.m16n8k8.row.col.f32.tf32.tf32.f32 "
        "{%0,%1,%2,%3},{%4,%5,%6,%7},{%8,%9},{%0,%1,%2,%3};"
        : "+f"(d[0]), "+f"(d[1]), "+f"(d[2]), "+f"(d[3])
        : "r"(a0), "r"(a1), "r"(a2), "r"(a3), "r"(b0), "r"(b1));
}

__device__ __forceinline__ void ldm_x4(uint32_t& r0, uint32_t& r1,
                                       uint32_t& r2, uint32_t& r3, uint32_t addr)
{
    asm volatile("ldmatrix.sync.aligned.m8n8.x4.shared.b16 {%0,%1,%2,%3}, [%4];"
        : "=r"(r0), "=r"(r1), "=r"(r2), "=r"(r3) : "r"(addr));
}

// ---------------- smem layout (float offsets) ----------------
// Qlo and P are fragment-packed: block(grp, mi) = 128B contiguous,
// grp = rblk*4 + (kk|ks), mi in {a0,a1,a2,a3}; 8*4 grps * 4 mi * 32 words = 4096 w.
#define OFF_QLO  0                                    // 4608 (4096 used)
#define OFF_KH(bf) (4608 + (bf) * 2304)
#define OFF_KL(bf) (4608 + (bf) * 2304 + 1152)
#define OFF_P(bf)  (9216 + (bf) * 4608)               // 4096 used
#define OFF_V(bf)  (18432 + (bf) * 8448)              // 32*264, 3 buffers
#define OFF_LSUM   43776                              // 2*128
#define SMEM_FLOATS 44032                             // 176128 bytes

// ---------------------------------------------------------------------------
// proj_qk: hi/lo tf32 split planes [b][n][32]
// ---------------------------------------------------------------------------
__global__ __launch_bounds__(256) void proj_qk(
    const float* __restrict__ X, const float* __restrict__ W,
    const float* __restrict__ bias,
    float* __restrict__ o_hi, float* __restrict__ o_lo)
{
    const int b  = blockIdx.z;
    const int n0 = blockIdx.x * 128;
    const int t  = threadIdx.x;
    const int tx = t & 31;
    const int ty = t >> 5;

    __shared__ float As[32][128];
    __shared__ float Bs[32][32];

    float acc[4][4];
#pragma unroll
    for (int i = 0; i < 4; i++)
#pragma unroll
        for (int u = 0; u < 4; u++) acc[i][u] = 0.f;

    const float* Xb = X + b * CC * NN;
    for (int c0 = 0; c0 < CC; c0 += 32) {
#pragma unroll
        for (int i = 0; i < 4; i++) {
            int idx = t + 256 * i;
            int cc  = idx >> 5;
            int nn  = (idx & 31) * 4;
            *(float4*)&As[cc][nn] = *(const float4*)(Xb + (c0 + cc) * NN + n0 + nn);
        }
        {
            int jj = t >> 3;
            int c4 = (t & 7) * 4;
            *(float4*)&Bs[jj][c4] = *(const float4*)(W + jj * CC + c0 + c4);
        }
        __syncthreads();
#pragma unroll
        for (int cc = 0; cc < 32; cc++) {
            float4 a = *(const float4*)&As[cc][tx * 4];
            float b0 = Bs[ty * 4 + 0][cc];
            float b1 = Bs[ty * 4 + 1][cc];
            float b2 = Bs[ty * 4 + 2][cc];
            float b3 = Bs[ty * 4 + 3][cc];
            acc[0][0] += a.x * b0; acc[0][1] += a.x * b1; acc[0][2] += a.x * b2; acc[0][3] += a.x * b3;
            acc[1][0] += a.y * b0; acc[1][1] += a.y * b1; acc[1][2] += a.y * b2; acc[1][3] += a.y * b3;
            acc[2][0] += a.z * b0; acc[2][1] += a.z * b1; acc[2][2] += a.z * b2; acc[2][3] += a.z * b3;
            acc[3][0] += a.w * b0; acc[3][1] += a.w * b1; acc[3][2] += a.w * b2; acc[3][3] += a.w * b3;
        }
        __syncthreads();
    }

    float bj[4] = { bias[ty*4], bias[ty*4+1], bias[ty*4+2], bias[ty*4+3] };
#pragma unroll
    for (int i = 0; i < 4; i++) {
        int n = n0 + tx * 4 + i;
        uint4 hi, lo;
        float v0 = acc[i][0] + bj[0];
        float v1 = acc[i][1] + bj[1];
        float v2 = acc[i][2] + bj[2];
        float v3 = acc[i][3] + bj[3];
        hi.x = f2tf32(v0); lo.x = f2tf32(v0 - __uint_as_float(hi.x));
        hi.y = f2tf32(v1); lo.y = f2tf32(v1 - __uint_as_float(hi.y));
        hi.z = f2tf32(v2); lo.z = f2tf32(v2 - __uint_as_float(hi.z));
        hi.w = f2tf32(v3); lo.w = f2tf32(v3 - __uint_as_float(hi.w));
        *(uint4*)(o_hi + ((size_t)b * NN + n) * DQK + ty * 4) = hi;
        *(uint4*)(o_lo + ((size_t)b * NN + n) * DQK + ty * 4) = lo;
    }
}

// ---------------------------------------------------------------------------
// proj_v: V projection, tf32-rounded, row-major [b][n][256]
// ---------------------------------------------------------------------------
__global__ __launch_bounds__(256) void proj_v(
    const float* __restrict__ X, const float* __restrict__ W,
    const float* __restrict__ bias, float* __restrict__ outv)
{
    const int b  = blockIdx.z;
    const int n0 = blockIdx.x * 128;
    const int j0 = blockIdx.y * 32;
    const int t  = threadIdx.x;
    const int tx = t & 31;
    const int ty = t >> 5;

    __shared__ float As[32][128];
    __shared__ float Bs[32][32];

    float acc[4][4];
#pragma unroll
    for (int i = 0; i < 4; i++)
#pragma unroll
        for (int u = 0; u < 4; u++) acc[i][u] = 0.f;

    const float* Xb = X + b * CC * NN;
    for (int c0 = 0; c0 < CC; c0 += 32) {
#pragma unroll
        for (int i = 0; i < 4; i++) {
            int idx = t + 256 * i;
            int cc  = idx >> 5;
            int nn  = (idx & 31) * 4;
            *(float4*)&As[cc][nn] = *(const float4*)(Xb + (c0 + cc) * NN + n0 + nn);
        }
        {
            int jj = t >> 3;
            int c4 = (t & 7) * 4;
            *(float4*)&Bs[jj][c4] = *(const float4*)(W + (j0 + jj) * CC + c0 + c4);
        }
        __syncthreads();
#pragma unroll
        for (int cc = 0; cc < 32; cc++) {
            float4 a = *(const float4*)&As[cc][tx * 4];
            float b0 = Bs[ty * 4 + 0][cc];
            float b1 = Bs[ty * 4 + 1][cc];
            float b2 = Bs[ty * 4 + 2][cc];
            float b3 = Bs[ty * 4 + 3][cc];
            acc[0][0] += a.x * b0; acc[0][1] += a.x * b1; acc[0][2] += a.x * b2; acc[0][3] += a.x * b3;
            acc[1][0] += a.y * b0; acc[1][1] += a.y * b1; acc[1][2] += a.y * b2; acc[1][3] += a.y * b3;
            acc[2][0] += a.z * b0; acc[2][1] += a.z * b1; acc[2][2] += a.z * b2; acc[2][3] += a.z * b3;
            acc[3][0] += a.w * b0; acc[3][1] += a.w * b1; acc[3][2] += a.w * b2; acc[3][3] += a.w * b3;
        }
        __syncthreads();
    }

    float bj[4] = { bias[j0+ty*4], bias[j0+ty*4+1], bias[j0+ty*4+2], bias[j0+ty*4+3] };
#pragma unroll
    for (int i = 0; i < 4; i++) {
        int n = n0 + tx * 4 + i;
        uint4 r;
        r.x = f2tf32(acc[i][0] + bj[0]);
        r.y = f2tf32(acc[i][1] + bj[1]);
        r.z = f2tf32(acc[i][2] + bj[2]);
        r.w = f2tf32(acc[i][3] + bj[3]);
        *(uint4*)(outv + ((size_t)b * NN + n) * CC + j0 + ty * 4) = r;
    }
}

// ---------------------------------------------------------------------------
// Flash attention (R14 structure + fragment-packed P/Qlo read via ldmatrix).
// ---------------------------------------------------------------------------
__global__ __launch_bounds__(THREADS) void flash_kernel(float* __restrict__ out)
{
    extern __shared__ float sm[];
    const uint32_t smem = smem_u32(sm);

    const int b    = blockIdx.y;
    const int n0   = blockIdx.x * TQ;
    const int t    = threadIdx.x;
    const int w    = t >> 5;
    const int lane = t & 31;
    const int gid  = lane >> 2;
    const int tid  = lane & 3;
    // S mapping
    const int ms = (w & 7) * 16;
    const int nh = (w >> 3) * 16;
    const int rblkS  = w & 7;
    const int ksbase = (w >> 3) * 2;
    const int chi    = tid >> 1;
    // PV mapping: 64 rows x 32 channels per warp
    const int rg = (w & 1) * 64;
    const int cg = (w >> 1) * 32;

    // ldmatrix per-lane offset: matrix (lane>>3), row (lane&7)
    const uint32_t lmoff = ((lane >> 3) * 128) + ((lane & 7) * 16);
    const uint32_t qlo_lm = smem + OFF_QLO * 4 + rblkS * 2048 + lmoff;
    const uint32_t p_lm[2] = { smem + OFF_P(0) * 4 + (w & 1) * 8192 + lmoff,
                               smem + OFF_P(1) * 4 + (w & 1) * 8192 + lmoff };

    const float* gqh = g_qh + ((size_t)b * NN + n0) * DQK;
    const float* gql = g_ql + ((size_t)b * NN + n0) * DQK;
    const float* gkh = g_kh + (size_t)b * NN * DQK;
    const float* gkl = g_kl + (size_t)b * NN * DQK;
    const float* gv  = g_v  + (size_t)b * NN * CC;

    float*    Qlo  = sm + OFF_QLO;
    float*    lsum = sm + OFF_LSUM;
    uint32_t* Pb[2]  = { (uint32_t*)(sm + OFF_P(0)), (uint32_t*)(sm + OFF_P(1)) };
    uint32_t* Vb[3]  = { (uint32_t*)(sm + OFF_V(0)), (uint32_t*)(sm + OFF_V(1)),
                         (uint32_t*)(sm + OFF_V(2)) };
    uint32_t* Khb[2] = { (uint32_t*)(sm + OFF_KH(0)), (uint32_t*)(sm + OFF_KH(1)) };
    uint32_t* Klb[2] = { (uint32_t*)(sm + OFF_KL(0)), (uint32_t*)(sm + OFF_KL(1)) };

    // --- Q fragments: qhi regs (all warps); qlo fragment-packed (warps 0-7) ---
    uint32_t qhi[4][4];
    {
        const float* q0 = gqh + (size_t)(ms + gid) * DQK;
        const float* q1 = q0 + 8 * DQK;
        const float* l0 = gql + (size_t)(ms + gid) * DQK;
        const float* l1 = l0 + 8 * DQK;
#pragma unroll
        for (int kk = 0; kk < 4; kk++) {
            qhi[kk][0] = __float_as_uint(__ldg(q0 + kk * 8 + tid));
            qhi[kk][1] = __float_as_uint(__ldg(q1 + kk * 8 + tid));
            qhi[kk][2] = __float_as_uint(__ldg(q0 + kk * 8 + tid + 4));
            qhi[kk][3] = __float_as_uint(__ldg(q1 + kk * 8 + tid + 4));
            if (w < 8) {
                // fragment-packed: block grp=(rblkS*4+kk), mi=0..3, word=gid*4+tid
                int bw = (rblkS * 4 + kk) * 128 + gid * 4 + tid;
                Qlo[bw]      = __ldg(l0 + kk * 8 + tid);
                Qlo[bw + 32] = __ldg(l1 + kk * 8 + tid);
                Qlo[bw + 64] = __ldg(l0 + kk * 8 + tid + 4);
                Qlo[bw + 96] = __ldg(l1 + kk * 8 + tid + 4);
            }
        }
    }

    float acc[4][4][4];
#pragma unroll
    for (int it = 0; it < 4; it++)
#pragma unroll
        for (int jt = 0; jt < 4; jt++)
#pragma unroll
            for (int u = 0; u < 4; u++) acc[it][jt][u] = 0.f;

    float lrun_lo = 0.f, lrun_hi = 0.f;

    auto stage_k = [&](int kt_idx, int bf) {
        const int plane = t >> 8;
        const int m = (t >> 3) & 31;
        const int c = t & 7;
        const float* src = (plane ? gkl : gkh) + (size_t)(kt_idx * KT + m) * DQK + c * 4;
        const uint32_t base = plane ? (smem + OFF_KL(bf) * 4) : (smem + OFF_KH(bf) * 4);
        cp16(base + (m * KSTR + c * 4) * 4, src);
    };
    auto stage_v = [&](int kt_idx, int bf) {
        const uint32_t base = smem + OFF_V(bf) * 4;
#pragma unroll
        for (int i = 0; i < 4; i++) {
            int ch = t + THREADS * i;
            int m  = ch >> 6;
            int c4 = (ch & 63) * 4;
            cp16(base + (m * VSTR + c4) * 4, gv + (size_t)(kt_idx * KT + m) * CC + c4);
        }
    };

    // --- S phase: split-tf32 3-pass; qlo via ldmatrix; P stored frag-packed ---
    auto s_phase = [&](const uint32_t* Kh, const uint32_t* Kl, uint32_t* Pw) {
        float sf[2][4];
#pragma unroll
        for (int j = 0; j < 2; j++)
#pragma unroll
            for (int u = 0; u < 4; u++) sf[j][u] = 0.f;

#pragma unroll
        for (int kk = 0; kk < 4; kk++) {
            uint32_t ql0, ql1, ql2, ql3;
            ldm_x4(ql0, ql1, ql2, ql3, qlo_lm + kk * 512);
#pragma unroll
            for (int j = 0; j < 2; j++) {
                const int cn = nh + 8 * j + gid;
                uint32_t bh0 = Kh[cn * KSTR + kk * 8 + tid];
                uint32_t bh1 = Kh[cn * KSTR + kk * 8 + tid + 4];
                uint32_t bl0 = Kl[cn * KSTR + kk * 8 + tid];
                uint32_t bl1 = Kl[cn * KSTR + kk * 8 + tid + 4];
                mma_tf32(sf[j], qhi[kk][0], qhi[kk][1], qhi[kk][2], qhi[kk][3], bh0, bh1);
                mma_tf32(sf[j], ql0, ql1, ql2, ql3, bh0, bh1);
                mma_tf32(sf[j], qhi[kk][0], qhi[kk][1], qhi[kk][2], qhi[kk][3], bl0, bl1);
            }
        }

#pragma unroll
        for (int j = 0; j < 2; j++) {
            float e0 = __expf(sf[j][0]);
            float e1 = __expf(sf[j][1]);
            float e2 = __expf(sf[j][2]);
            float e3 = __expf(sf[j][3]);
            lrun_lo += e0 + e1;
            lrun_hi += e2 + e3;
            uint2 plo, phi;
            plo.x = f2tf32(e0); plo.y = f2tf32(e1);
            phi.x = f2tf32(e2); phi.y = f2tf32(e3);
            // fragment-packed store: grp=(rblkS*4 + ksbase+j), mi = 2*chi (+1 hi)
            int bw = ((rblkS * 4 + ksbase + j) * 4 + 2 * chi) * 32 + gid * 4 + (tid & 1) * 2;
            *(uint2*)&Pw[bw]      = plo;
            *(uint2*)&Pw[bw + 32] = phi;
        }
    };

    // --- PV phase: A-frags via ldmatrix from packed P ---
    auto pv_phase = [&](uint32_t plm, const uint32_t* V) {
#pragma unroll
        for (int ks = 0; ks < 4; ks++) {
            const int m0 = ks * 8;
            uint32_t b0[4], b1[4];
#pragma unroll
            for (int jt = 0; jt < 4; jt++) {
                b0[jt] = V[(m0 + tid)     * VSTR + cg + jt * 8 + gid];
                b1[jt] = V[(m0 + tid + 4) * VSTR + cg + jt * 8 + gid];
            }
#pragma unroll
            for (int it = 0; it < 4; it++) {
                uint32_t a0, a1, a2, a3;
                ldm_x4(a0, a1, a2, a3, plm + it * 2048 + ks * 512);
#pragma unroll
                for (int jt = 0; jt < 4; jt++)
                    mma_tf32(acc[it][jt], a0, a1, a2, a3, b0[jt], b1[jt]);
            }
        }
    };

    // --- prologue ---
    stage_k(0, 0);
    stage_k(1, 1);
    stage_v(0, 0);
    stage_v(1, 1);
    CP_COMMIT();
    CP_WAIT0();
    __syncthreads();
    s_phase(Khb[0], Klb[0], Pb[0]);
    __syncthreads();

    // --- main loop ---
    int v_rd = 0, v_wr = 2;
    for (int kt = 0; kt < NKT; kt++) {
        const int buf = kt & 1;

        if (kt + 2 < NKT) {
            stage_k(kt + 2, buf);
            stage_v(kt + 2, v_wr);
        }
        CP_COMMIT();

        pv_phase(p_lm[buf], Vb[v_rd]);

        CP_WAIT1();                      // group(kt-1): K(kt+1), V(kt+1) done

        if (kt + 1 < NKT)
            s_phase(Khb[buf ^ 1], Klb[buf ^ 1], Pb[buf ^ 1]);

        __syncthreads();
        v_rd = (v_rd == 2) ? 0 : v_rd + 1;
        v_wr = (v_wr == 2) ? 0 : v_wr + 1;
    }

    // --- row-sum reduction ---
    lrun_lo += __shfl_xor_sync(0xffffffffu, lrun_lo, 1);
    lrun_lo += __shfl_xor_sync(0xffffffffu, lrun_lo, 2);
    lrun_hi += __shfl_xor_sync(0xffffffffu, lrun_hi, 1);
    lrun_hi += __shfl_xor_sync(0xffffffffu, lrun_hi, 2);
    if (tid == 0) {
        lsum[(w >> 3) * 128 + ms + gid]     = lrun_lo;
        lsum[(w >> 3) * 128 + ms + gid + 8] = lrun_hi;
    }
    __syncthreads();
    if (t < 128) Qlo[t] = 1.f / (lsum[t] + lsum[128 + t]);   // reuse Qlo as inv
    __syncthreads();

    // --- epilogue: out[b][c][n0+r] ---
    float* ob = out + (size_t)b * CC * NN + n0;
#pragma unroll
    for (int it = 0; it < 4; it++) {
        const int r_lo = rg + it * 16 + gid;
        const int r_hi = r_lo + 8;
        const float ilo = Qlo[r_lo];
        const float ihi = Qlo[r_hi];
#pragma unroll
        for (int jt = 0; jt < 4; jt++) {
            const int c0 = cg + jt * 8 + tid * 2;
            ob[(size_t)(c0    ) * NN + r_lo] = acc[it][jt][0] * ilo;
            ob[(size_t)(c0 + 1) * NN + r_lo] = acc[it][jt][1] * ilo;
            ob[(size_t)(c0    ) * NN + r_hi] = acc[it][jt][2] * ihi;
            ob[(size_t)(c0 + 1) * NN + r_hi] = acc[it][jt][3] * ihi;
        }
    }
}

// ---------------------------------------------------------------------------
extern "C" void kernel_launch(void* const* d_in, const int* in_sizes, int n_in,
                              void* d_out, int out_size)
{
    const float* f1 = (const float*)d_in[0];
    const float* f2 = (const float*)d_in[1];
    const float* Wq = (const float*)d_in[2];
    const float* bq = (const float*)d_in[3];
    const float* Wk = (const float*)d_in[4];
    const float* bk = (const float*)d_in[5];
    const float* Wv = (const float*)d_in[6];
    const float* bv = (const float*)d_in[7];
    float* out = (float*)d_out;

    float *qh, *ql, *kh, *kl, *vp;
    cudaGetSymbolAddress((void**)&qh, g_qh);
    cudaGetSymbolAddress((void**)&ql, g_ql);
    cudaGetSymbolAddress((void**)&kh, g_kh);
    cudaGetSymbolAddress((void**)&kl, g_kl);
    cudaGetSymbolAddress((void**)&vp, g_v);

    const int smem_bytes = SMEM_FLOATS * (int)sizeof(float);
    cudaFuncSetAttribute(flash_kernel,
                         cudaFuncAttributeMaxDynamicSharedMemorySize, smem_bytes);

    proj_qk<<<dim3(NN / 128, 1, BB), 256>>>(f1, Wq, bq, qh, ql);
    proj_qk<<<dim3(NN / 128, 1, BB), 256>>>(f2, Wk, bk, kh, kl);
    proj_v <<<dim3(NN / 128, 8, BB), 256>>>(f2, Wv, bv, vp);
    flash_kernel<<<dim3(NN / TQ, BB), THREADS, smem_bytes>>>(out);
}